// round 11
// baseline (speedup 1.0000x reference)
#include <cuda_runtime.h>
#include <cuda_fp16.h>
#include <cstdint>

// ---------------- Problem constants ----------------
#define B_SZ   128
#define D1     320
#define C_MAX  272
#define T_LEN  512

#define NSTAGE 9            // K covered by 9 stages of 32 (last stage: only 16 real k)
#define NK16   17           // real k16 count: 272 / 16
#define NTILES 4            // 512 / 128

// W fragments: per (s,ks): 20 m16 * 2 k16 * 32 lanes * 16B = 20480 B
#define WSTAGE_B 20480
__device__ __align__(128) unsigned char g_Wh[(size_t)8 * NSTAGE * WSTAGE_B];   // ~1.5 MB

// ---------------- helpers ----------------
__device__ __forceinline__ uint32_t smem_u32(const void* p) {
    uint32_t a;
    asm("{ .reg .u64 t; cvta.to.shared.u64 t, %1; cvt.u32.u64 %0, t; }" : "=r"(a) : "l"(p));
    return a;
}
__device__ __forceinline__ uint32_t pack_h2(float lo, float hi) {
    __half2 h = __floats2half2_rn(lo, hi);
    return *reinterpret_cast<uint32_t*>(&h);
}
__device__ __forceinline__ void cp16p(uint32_t dst, const void* src, int bytes) {
    asm volatile("cp.async.cg.shared.global [%0], [%1], 16, %2;"
                 :: "r"(dst), "l"(src), "r"(bytes));
}
#define CP_COMMIT() asm volatile("cp.async.commit_group;" ::: "memory")
#define CP_WAIT(n)  asm volatile("cp.async.wait_group %0;" :: "n"(n) : "memory")

__device__ __forceinline__ void ldg128(uint32_t* r, const void* p) {
    asm volatile("ld.global.nc.v4.b32 {%0,%1,%2,%3}, [%4];"
                 : "=r"(r[0]), "=r"(r[1]), "=r"(r[2]), "=r"(r[3]) : "l"(p));
}
__device__ __forceinline__ void lds64(uint32_t* r, uint32_t addr) {
    asm volatile("ld.shared.v2.b32 {%0,%1}, [%2];"
                 : "=r"(r[0]), "=r"(r[1]) : "r"(addr));
}
__device__ __forceinline__ void sts64(uint32_t addr, uint32_t v0, uint32_t v1) {
    asm volatile("st.shared.v2.b32 [%0], {%1,%2};" :: "r"(addr), "r"(v0), "r"(v1) : "memory");
}
__device__ __forceinline__ void mma16816(float* c, const uint32_t* a, const uint32_t* b) {
    asm volatile(
        "mma.sync.aligned.m16n8k16.row.col.f32.f16.f16.f32 "
        "{%0,%1,%2,%3}, {%4,%5,%6,%7}, {%8,%9}, {%0,%1,%2,%3};"
        : "+f"(c[0]), "+f"(c[1]), "+f"(c[2]), "+f"(c[3])
        : "r"(a[0]), "r"(a[1]), "r"(a[2]), "r"(a[3]), "r"(b[0]), "r"(b[1]));
}

// ---------------- prep_w: W -> fp16 A-fragments (L2-hot, tiny) ----------------
__global__ __launch_bounds__(256) void prep_w(const float* __restrict__ W) {
    const int ks = blockIdx.x;          // 0..8
    const int mg = blockIdx.y;          // 0..3  (5 m16 each)
    const int s  = blockIdx.z;          // 0..7
    const float* ws = W + (size_t)s * D1 * C_MAX;
    uint4* wd = (uint4*)(g_Wh + ((size_t)s * NSTAGE + ks) * WSTAGE_B);

    const int tid = threadIdx.x;
    #pragma unroll
    for (int it = 0; it < 2; it++) {
        const int j = tid + it * 256;          // 0..319
        if (j >= 320) break;
        const int lane = j & 31;
        const int k16  = (j >> 5) & 1;
        const int m16  = mg * 5 + (j >> 6);    // 0..19
        const int g    = lane >> 2;
        const int k0   = ks * 32 + k16 * 16 + (lane & 3) * 2;
        const int mA   = m16 * 16 + g;

        uint32_t r[4];
        #pragma unroll
        for (int rr = 0; rr < 4; rr++) {
            const int m = mA + (rr & 1) * 8;
            const int k = k0 + (rr >> 1) * 8;
            float v0 = (k     < C_MAX) ? ws[(size_t)m * C_MAX + k    ] : 0.0f;
            float v1 = (k + 1 < C_MAX) ? ws[(size_t)m * C_MAX + k + 1] : 0.0f;
            r[rr] = pack_h2(v0, v1);
        }
        uint4 o; o.x = r[0]; o.y = r[1]; o.z = r[2]; o.w = r[3];
        wd[(size_t)(m16 * 2 + k16) * 32 + lane] = o;
    }
}

// ---------------- Fused GEMM ----------------
#define BFRAG_SZ  (NSTAGE * 8192)
#define SLAB_SZ   16896
#define GEMM_SMEM (BFRAG_SZ + 2 * SLAB_SZ)    // 107520

// A fragment address for (kk, mi): base + (kk>>1)*WSTAGE_B + (kk&1)*512 + mi*1024
template <int MCNT>
__device__ __forceinline__ void gemm_pass(
    uint32_t bfrag, const unsigned char* srcA, int m16base,
    float* __restrict__ orow0, int lane, int wid)
{
    constexpr int MW  = MCNT / 2;     // m-warp groups
    constexpr int NW  = 8 / MW;       // n-warp groups
    constexpr int N8W = 16 / NW;      // n8 per warp
    const int wm = wid % MW;
    const int wn = wid / MW;

    float acc[2][N8W][4];
    #pragma unroll
    for (int i = 0; i < 2; i++)
        #pragma unroll
        for (int j = 0; j < N8W; j++)
            #pragma unroll
            for (int q = 0; q < 4; q++) acc[i][j][q] = 0.0f;

    // Per-warp A base (covers both mi via +1024)
    const unsigned char* aBase = srcA + (size_t)(m16base + 2 * wm) * 1024 + (size_t)lane * 16;
    const uint32_t bWarp = bfrag + (uint32_t)(wn * N8W * 256) + (uint32_t)lane * 8;

    // Software pipeline: double-buffered A fragments in registers.
    uint32_t afr[2][2][4];
    {
        // kk = 0
        ldg128(afr[0][0], aBase);
        ldg128(afr[0][1], aBase + 1024);
    }

    #pragma unroll 1
    for (int kk = 0; kk < NK16; kk++) {
        const int cur = kk & 1;
        // Prefetch A for kk+1
        if (kk + 1 < NK16) {
            const unsigned char* aN = aBase + (size_t)((kk + 1) >> 1) * WSTAGE_B
                                            + (size_t)((kk + 1) & 1) * 512;
            ldg128(afr[cur ^ 1][0], aN);
            ldg128(afr[cur ^ 1][1], aN + 1024);
        }

        // B fragments for kk (smem, low latency)
        const uint32_t bS = bWarp + (uint32_t)((kk >> 1) * 8192 + (kk & 1) * 4096);
        uint32_t bfr[N8W][2];
        #pragma unroll
        for (int ni = 0; ni < N8W; ni++)
            lds64(bfr[ni], bS + (uint32_t)(ni * 256));

        #pragma unroll
        for (int mi = 0; mi < 2; mi++)
            #pragma unroll
            for (int ni = 0; ni < N8W; ni++)
                mma16816(acc[mi][ni], afr[cur][mi], bfr[ni]);
    }

    // epilogue
    const int g  = lane >> 2;
    const int c2 = (lane & 3) * 2;
    const int col0 = wn * (N8W * 8) + c2;
    #pragma unroll
    for (int mi = 0; mi < 2; mi++) {
        const int row = m16base * 16 + wm * 32 + mi * 16 + g;
        float* o0 = orow0 + (size_t)row * T_LEN + col0;
        float* o1 = orow0 + (size_t)(row + 8) * T_LEN + col0;
        #pragma unroll
        for (int ni = 0; ni < N8W; ni++) {
            float2 v0; v0.x = acc[mi][ni][0]; v0.y = acc[mi][ni][1];
            float2 v1; v1.x = acc[mi][ni][2]; v1.y = acc[mi][ni][3];
            *(float2*)(o0 + ni * 8) = v0;
            *(float2*)(o1 + ni * 8) = v1;
        }
    }
}

__global__ __launch_bounds__(256, 2) void gemm_fused(const float* __restrict__ X,
                                                     const int* __restrict__ subj,
                                                     float* __restrict__ out) {
    extern __shared__ unsigned char dsm[];
    const uint32_t sbase = smem_u32(dsm);
    const uint32_t bfrag = sbase;

    const int tid  = threadIdx.x;
    const int lane = tid & 31;
    const int wid  = tid >> 5;
    const int nt = blockIdx.x, b = blockIdx.z;
    const int s  = subj[b];

    const float* xb = X + (size_t)b * C_MAX * T_LEN + (size_t)nt * 128;

    // ---- Phase 1: convert X [272 x 128] slice -> fp16 B fragments in smem ----
    float* slab[2] = { (float*)(dsm + BFRAG_SZ), (float*)(dsm + BFRAG_SZ + SLAB_SZ) };

    auto load_slab = [&](int ks) {
        const uint32_t d = sbase + BFRAG_SZ + (uint32_t)(ks & 1) * SLAB_SZ;
        const int c0 = ks * 32;
        #pragma unroll
        for (int it = 0; it < 4; it++) {
            const int idx = tid + it * 256;        // 0..1023
            const int cl  = idx >> 5;
            const int t4  = (idx & 31) * 4;
            const int ok  = (c0 + cl < C_MAX) ? 16 : 0;
            cp16p(d + (uint32_t)(cl * 132 + t4) * 4,
                  xb + (size_t)(c0 + cl) * T_LEN + t4, ok);
        }
    };

    load_slab(0); CP_COMMIT();
    #pragma unroll 1
    for (int ks = 0; ks < NSTAGE; ks++) {
        if (ks + 1 < NSTAGE) { load_slab(ks + 1); CP_COMMIT(); CP_WAIT(1); }
        else                 { CP_WAIT(0); }
        __syncthreads();

        const float* sl = slab[ks & 1];
        #pragma unroll
        for (int it = 0; it < 4; it++) {
            const int j    = tid + it * 256;       // 0..1023
            const int ln   = j & 31;
            const int n8   = (j >> 5) & 15;
            const int k16  = j >> 9;
            const int t    = n8 * 8 + (ln >> 2);
            const int kc   = k16 * 16 + (ln & 3) * 2;
            uint32_t v0 = pack_h2(sl[kc * 132 + t],       sl[(kc + 1) * 132 + t]);
            uint32_t v1 = pack_h2(sl[(kc + 8) * 132 + t], sl[(kc + 9) * 132 + t]);
            sts64(bfrag + (uint32_t)(ks * 8192) + (uint32_t)j * 8, v0, v1);
        }
        __syncthreads();
    }

    // ---- Phase 2: three m-passes against resident B (sync-free, A pipelined) ----
    const unsigned char* srcA = g_Wh + (size_t)s * NSTAGE * WSTAGE_B;
    float* orow0 = out + (size_t)b * D1 * T_LEN + nt * 128;

    gemm_pass<8>(bfrag, srcA, 0,  orow0, lane, wid);   // rows   0..127
    gemm_pass<8>(bfrag, srcA, 8,  orow0, lane, wid);   // rows 128..255
    gemm_pass<4>(bfrag, srcA, 16, orow0, lane, wid);   // rows 256..319
}

// ---------------- Host launcher ----------------
extern "C" void kernel_launch(void* const* d_in, const int* in_sizes, int n_in,
                              void* d_out, int out_size) {
    const float* X    = (const float*)d_in[0];  // [128, 272, 512]
    const int*   subj = (const int*)  d_in[1];  // [128]
    const float* W    = (const float*)d_in[2];  // [8, 320, 272]
    float*       out  = (float*)d_out;          // [128, 320, 512]

    cudaFuncSetAttribute(gemm_fused, cudaFuncAttributeMaxDynamicSharedMemorySize, GEMM_SMEM);

    prep_w<<<dim3(NSTAGE, 4, 8), 256>>>(W);
    gemm_fused<<<dim3(NTILES, 1, B_SZ), 256, GEMM_SMEM>>>(X, subj, out);
}

// round 12
// speedup vs baseline: 1.4245x; 1.4245x over previous
#include <cuda_runtime.h>
#include <cuda_fp16.h>
#include <cstdint>

// ---------------- Problem constants ----------------
#define B_SZ   128
#define D1     320
#define C_MAX  272
#define T_LEN  512

#define NSTAGE 9            // K covered by 9 stages of 32 (last stage: only 16 real k)
#define NTILES 4            // 512 / 128

// W fragments: per (s,ks): 20 m16 * 2 k16 * 32 lanes * 16B = 20480 B
#define WSTAGE_B 20480
__device__ __align__(128) unsigned char g_Wh[(size_t)8 * NSTAGE * WSTAGE_B];   // ~1.5 MB

// ---------------- helpers ----------------
__device__ __forceinline__ uint32_t smem_u32(const void* p) {
    uint32_t a;
    asm("{ .reg .u64 t; cvta.to.shared.u64 t, %1; cvt.u32.u64 %0, t; }" : "=r"(a) : "l"(p));
    return a;
}
__device__ __forceinline__ uint32_t pack_h2(float lo, float hi) {
    __half2 h = __floats2half2_rn(lo, hi);
    return *reinterpret_cast<uint32_t*>(&h);
}
__device__ __forceinline__ void cp16(uint32_t dst, const void* src) {
    asm volatile("cp.async.cg.shared.global [%0], [%1], 16;" :: "r"(dst), "l"(src));
}
__device__ __forceinline__ void cp16p(uint32_t dst, const void* src, int bytes) {
    asm volatile("cp.async.cg.shared.global [%0], [%1], 16, %2;"
                 :: "r"(dst), "l"(src), "r"(bytes));
}
#define CP_COMMIT() asm volatile("cp.async.commit_group;" ::: "memory")
#define CP_WAIT(n)  asm volatile("cp.async.wait_group %0;" :: "n"(n) : "memory")

__device__ __forceinline__ void lds128(uint32_t* r, uint32_t addr) {
    asm volatile("ld.shared.v4.b32 {%0,%1,%2,%3}, [%4];"
                 : "=r"(r[0]), "=r"(r[1]), "=r"(r[2]), "=r"(r[3]) : "r"(addr));
}
__device__ __forceinline__ void lds64(uint32_t* r, uint32_t addr) {
    asm volatile("ld.shared.v2.b32 {%0,%1}, [%2];"
                 : "=r"(r[0]), "=r"(r[1]) : "r"(addr));
}
__device__ __forceinline__ void sts64(uint32_t addr, uint32_t v0, uint32_t v1) {
    asm volatile("st.shared.v2.b32 [%0], {%1,%2};" :: "r"(addr), "r"(v0), "r"(v1) : "memory");
}
__device__ __forceinline__ void mma16816(float* c, const uint32_t* a, const uint32_t* b) {
    asm volatile(
        "mma.sync.aligned.m16n8k16.row.col.f32.f16.f16.f32 "
        "{%0,%1,%2,%3}, {%4,%5,%6,%7}, {%8,%9}, {%0,%1,%2,%3};"
        : "+f"(c[0]), "+f"(c[1]), "+f"(c[2]), "+f"(c[3])
        : "r"(a[0]), "r"(a[1]), "r"(a[2]), "r"(a[3]), "r"(b[0]), "r"(b[1]));
}

// ---------------- prep_w: W -> fp16 A-fragments (L2-hot, tiny) ----------------
__global__ __launch_bounds__(256) void prep_w(const float* __restrict__ W) {
    const int ks = blockIdx.x;          // 0..8
    const int mg = blockIdx.y;          // 0..3  (5 m16 each)
    const int s  = blockIdx.z;          // 0..7
    const float* ws = W + (size_t)s * D1 * C_MAX;
    uint4* wd = (uint4*)(g_Wh + ((size_t)s * NSTAGE + ks) * WSTAGE_B);

    const int tid = threadIdx.x;
    #pragma unroll
    for (int it = 0; it < 2; it++) {
        const int j = tid + it * 256;          // 0..319
        if (j >= 320) break;
        const int lane = j & 31;
        const int k16  = (j >> 5) & 1;
        const int m16  = mg * 5 + (j >> 6);    // 0..19
        const int g    = lane >> 2;
        const int k0   = ks * 32 + k16 * 16 + (lane & 3) * 2;
        const int mA   = m16 * 16 + g;

        uint32_t r[4];
        #pragma unroll
        for (int rr = 0; rr < 4; rr++) {
            const int m = mA + (rr & 1) * 8;
            const int k = k0 + (rr >> 1) * 8;
            float v0 = (k     < C_MAX) ? ws[(size_t)m * C_MAX + k    ] : 0.0f;
            float v1 = (k + 1 < C_MAX) ? ws[(size_t)m * C_MAX + k + 1] : 0.0f;
            r[rr] = pack_h2(v0, v1);
        }
        uint4 o; o.x = r[0]; o.y = r[1]; o.z = r[2]; o.w = r[3];
        wd[(size_t)(m16 * 2 + k16) * 32 + lane] = o;
    }
}

// ---------------- Fused GEMM ----------------
#define BFRAG_SZ  (NSTAGE * 8192)            // 73728
#define SLAB_SZ   16896
#define ABUF_OFF  BFRAG_SZ                    // phase-2 A double-buffer (reuses slab space)
#define GEMM_SMEM (BFRAG_SZ + 2 * SLAB_SZ)    // 107520

// gemm_pass: A staged through smem (double-buffered cp.async), B resident in smem.
template <int MCNT>
__device__ __forceinline__ void gemm_pass(
    uint32_t sbase, const unsigned char* srcA, int m16base,
    float* __restrict__ orow0, int lane, int wid, int tid)
{
    constexpr int MW   = MCNT / 2;     // m-warp groups
    constexpr int NW   = 8 / MW;       // n-warp groups
    constexpr int N8W  = 16 / NW;      // n8 per warp
    constexpr int ASTG = MCNT * 1024;  // A stage bytes (8192 / 4096)
    constexpr int NCP  = ASTG / 16 / 256;  // cp16 per thread per stage (2 / 1)

    const int wm = wid % MW;
    const int wn = wid / MW;
    const uint32_t bfrag = sbase;
    const uint32_t abuf  = sbase + ABUF_OFF;

    float acc[2][N8W][4];
    #pragma unroll
    for (int i = 0; i < 2; i++)
        #pragma unroll
        for (int j = 0; j < N8W; j++)
            #pragma unroll
            for (int q = 0; q < 4; q++) acc[i][j][q] = 0.0f;

    auto cpA = [&](int ks) {
        const uint32_t d = abuf + (uint32_t)(ks & 1) * ASTG;
        const unsigned char* g = srcA + (size_t)ks * WSTAGE_B + (size_t)m16base * 1024;
        #pragma unroll
        for (int i = 0; i < NCP; i++)
            cp16(d + (uint32_t)(tid + i * 256) * 16, g + (size_t)(tid + i * 256) * 16);
        CP_COMMIT();
    };

    __syncthreads();           // protect abuf from previous pass's readers
    cpA(0);

    const uint32_t aWarp = abuf + (uint32_t)(2 * wm * 2) * 512 + (uint32_t)lane * 16;
    const uint32_t bWarp = bfrag + (uint32_t)(wn * N8W * 256) + (uint32_t)lane * 8;

    #pragma unroll 1
    for (int ks = 0; ks < NSTAGE; ks++) {
        CP_WAIT(0);
        __syncthreads();       // stage ks visible; prior stage's reads complete
        if (ks + 1 < NSTAGE) cpA(ks + 1);   // overlaps with compute below

        const uint32_t aS = aWarp + (uint32_t)(ks & 1) * ASTG;
        const uint32_t bS = bWarp + (uint32_t)(ks * 8192);

        #pragma unroll
        for (int k16 = 0; k16 < 2; k16++) {
            if (k16 == 1 && ks == NSTAGE - 1) break;   // K=272: last stage is half

            uint32_t afr[2][4];
            #pragma unroll
            for (int mi = 0; mi < 2; mi++)
                lds128(afr[mi], aS + (uint32_t)((mi * 2 + k16) * 512));

            uint32_t bfr[N8W][2];
            #pragma unroll
            for (int ni = 0; ni < N8W; ni++)
                lds64(bfr[ni], bS + (uint32_t)(k16 * 4096 + ni * 256));

            #pragma unroll
            for (int mi = 0; mi < 2; mi++)
                #pragma unroll
                for (int ni = 0; ni < N8W; ni++)
                    mma16816(acc[mi][ni], afr[mi], bfr[ni]);
        }
    }

    // epilogue
    const int g  = lane >> 2;
    const int c2 = (lane & 3) * 2;
    const int col0 = wn * (N8W * 8) + c2;
    #pragma unroll
    for (int mi = 0; mi < 2; mi++) {
        const int row = m16base * 16 + wm * 32 + mi * 16 + g;
        float* o0 = orow0 + (size_t)row * T_LEN + col0;
        float* o1 = orow0 + (size_t)(row + 8) * T_LEN + col0;
        #pragma unroll
        for (int ni = 0; ni < N8W; ni++) {
            float2 v0; v0.x = acc[mi][ni][0]; v0.y = acc[mi][ni][1];
            float2 v1; v1.x = acc[mi][ni][2]; v1.y = acc[mi][ni][3];
            *(float2*)(o0 + ni * 8) = v0;
            *(float2*)(o1 + ni * 8) = v1;
        }
    }
}

__global__ __launch_bounds__(256, 2) void gemm_fused(const float* __restrict__ X,
                                                     const int* __restrict__ subj,
                                                     float* __restrict__ out) {
    extern __shared__ unsigned char dsm[];
    const uint32_t sbase = smem_u32(dsm);
    const uint32_t bfrag = sbase;

    const int tid  = threadIdx.x;
    const int lane = tid & 31;
    const int wid  = tid >> 5;
    const int nt = blockIdx.x, b = blockIdx.z;
    const int s  = subj[b];

    const float* xb = X + (size_t)b * C_MAX * T_LEN + (size_t)nt * 128;

    // ---- Phase 1: convert X [272 x 128] slice -> fp16 B fragments in smem ----
    float* slab[2] = { (float*)(dsm + BFRAG_SZ), (float*)(dsm + BFRAG_SZ + SLAB_SZ) };

    auto load_slab = [&](int ks) {
        const uint32_t d = sbase + BFRAG_SZ + (uint32_t)(ks & 1) * SLAB_SZ;
        const int c0 = ks * 32;
        #pragma unroll
        for (int it = 0; it < 4; it++) {
            const int idx = tid + it * 256;        // 0..1023
            const int cl  = idx >> 5;
            const int t4  = (idx & 31) * 4;
            const int ok  = (c0 + cl < C_MAX) ? 16 : 0;
            cp16p(d + (uint32_t)(cl * 132 + t4) * 4,
                  xb + (size_t)(c0 + cl) * T_LEN + t4, ok);
        }
    };

    load_slab(0); CP_COMMIT();
    #pragma unroll 1
    for (int ks = 0; ks < NSTAGE; ks++) {
        if (ks + 1 < NSTAGE) { load_slab(ks + 1); CP_COMMIT(); CP_WAIT(1); }
        else                 { CP_WAIT(0); }
        __syncthreads();

        const float* sl = slab[ks & 1];
        #pragma unroll
        for (int it = 0; it < 4; it++) {
            const int j    = tid + it * 256;       // 0..1023
            const int ln   = j & 31;
            const int n8   = (j >> 5) & 15;
            const int k16  = j >> 9;
            const int t    = n8 * 8 + (ln >> 2);
            const int kc   = k16 * 16 + (ln & 3) * 2;
            uint32_t v0 = pack_h2(sl[kc * 132 + t],       sl[(kc + 1) * 132 + t]);
            uint32_t v1 = pack_h2(sl[(kc + 8) * 132 + t], sl[(kc + 9) * 132 + t]);
            sts64(bfrag + (uint32_t)(ks * 8192) + (uint32_t)j * 8, v0, v1);
        }
        __syncthreads();
    }

    // ---- Phase 2: three m-passes against resident B; A staged via smem ----
    const unsigned char* srcA = g_Wh + (size_t)s * NSTAGE * WSTAGE_B;
    float* orow0 = out + (size_t)b * D1 * T_LEN + nt * 128;

    gemm_pass<8>(sbase, srcA, 0,  orow0, lane, wid, tid);   // rows   0..127
    gemm_pass<8>(sbase, srcA, 8,  orow0, lane, wid, tid);   // rows 128..255
    gemm_pass<4>(sbase, srcA, 16, orow0, lane, wid, tid);   // rows 256..319
}

// ---------------- Host launcher ----------------
extern "C" void kernel_launch(void* const* d_in, const int* in_sizes, int n_in,
                              void* d_out, int out_size) {
    const float* X    = (const float*)d_in[0];  // [128, 272, 512]
    const int*   subj = (const int*)  d_in[1];  // [128]
    const float* W    = (const float*)d_in[2];  // [8, 320, 272]
    float*       out  = (float*)d_out;          // [128, 320, 512]

    cudaFuncSetAttribute(gemm_fused, cudaFuncAttributeMaxDynamicSharedMemorySize, GEMM_SMEM);

    prep_w<<<dim3(NSTAGE, 4, 8), 256>>>(W);
    gemm_fused<<<dim3(NTILES, 1, B_SZ), 256, GEMM_SMEM>>>(X, subj, out);
}